// round 6
// baseline (speedup 1.0000x reference)
#include <cuda_runtime.h>
#include <cuda_bf16.h>
#include <cstdint>

// Problem constants
#define Bn 64
#define Sn 512
#define Dn 256
#define Hn 256
#define Ln 9

// ---------------------------------------------------------------------------
// Static device scratch
// ---------------------------------------------------------------------------
__device__ float g_Xperm[2u * 512u * 64u * 1024u];      // 268 MB
__device__ float g_Hbuf[2u * 512u * 64u * 256u];        // 67 MB
__device__ float g_hstate[2][2][Bn * Hn];               // [parity][dir]
__device__ float g_em[(size_t)Bn * Sn * Ln];
__device__ float g_res[Bn];
__device__ volatile unsigned g_arrive[2][64];           // flag-array barrier

__device__ __forceinline__ float fsig(float x) { return 1.0f / (1.0f + __expf(-x)); }
__device__ __forceinline__ float ftanh(float x) { return 2.0f / (1.0f + __expf(-2.0f * x)) - 1.0f; }

__device__ __forceinline__ void cp_async16(uint32_t saddr, const void* gptr) {
    asm volatile("cp.async.cg.shared.global [%0], [%1], 16;" :: "r"(saddr), "l"(gptr));
}

// ---------------------------------------------------------------------------
// Kernel 1: embedding gather + input projection GEMM (+bias), permuted write.
// ---------------------------------------------------------------------------
__global__ void embed_inproj_kernel(const int* __restrict__ x,
                                    const float* __restrict__ E,
                                    const float* __restrict__ Wih_f,
                                    const float* __restrict__ b_f,
                                    const float* __restrict__ Wih_b,
                                    const float* __restrict__ b_b) {
    const int dir = blockIdx.z;
    const float* __restrict__ W = dir ? Wih_b : Wih_f;
    const float* __restrict__ bias = dir ? b_b : b_f;
    const int s = blockIdx.y;
    const int n0 = blockIdx.x * 64;

    __shared__ float sA[16][68];
    __shared__ float sB[16][68];
    __shared__ int srow[64];

    const int tid = threadIdx.x;
    if (tid < 64) srow[tid] = x[tid * Sn + s];
    __syncthreads();

    const int tm = tid & 15;
    const int tn = tid >> 4;
    const int lrow = tid >> 2;
    const int kq = tid & 3;

    float acc[4][4];
#pragma unroll
    for (int c = 0; c < 4; c++)
#pragma unroll
        for (int d = 0; d < 4; d++) acc[c][d] = 0.0f;

    for (int k0 = 0; k0 < 256; k0 += 16) {
        float4 a4 = *reinterpret_cast<const float4*>(&E[(size_t)srow[lrow] * Dn + k0 + kq * 4]);
        float4 b4 = *reinterpret_cast<const float4*>(&W[(size_t)(n0 + lrow) * Dn + k0 + kq * 4]);
        __syncthreads();
        sA[kq * 4 + 0][lrow] = a4.x; sA[kq * 4 + 1][lrow] = a4.y;
        sA[kq * 4 + 2][lrow] = a4.z; sA[kq * 4 + 3][lrow] = a4.w;
        sB[kq * 4 + 0][lrow] = b4.x; sB[kq * 4 + 1][lrow] = b4.y;
        sB[kq * 4 + 2][lrow] = b4.z; sB[kq * 4 + 3][lrow] = b4.w;
        __syncthreads();
#pragma unroll
        for (int kk = 0; kk < 16; kk++) {
            float4 ra = *reinterpret_cast<float4*>(&sA[kk][4 * tm]);
            float4 rb = *reinterpret_cast<float4*>(&sB[kk][4 * tn]);
            acc[0][0] += ra.x * rb.x; acc[0][1] += ra.x * rb.y; acc[0][2] += ra.x * rb.z; acc[0][3] += ra.x * rb.w;
            acc[1][0] += ra.y * rb.x; acc[1][1] += ra.y * rb.y; acc[1][2] += ra.y * rb.z; acc[1][3] += ra.y * rb.w;
            acc[2][0] += ra.z * rb.x; acc[2][1] += ra.z * rb.y; acc[2][2] += ra.z * rb.z; acc[2][3] += ra.z * rb.w;
            acc[3][0] += ra.w * rb.x; acc[3][1] += ra.w * rb.y; acc[3][2] += ra.w * rb.z; acc[3][3] += ra.w * rb.w;
        }
    }

    const int n = n0 + 4 * tn;
    const int blk = (n & 255) >> 2;
    const int mg = n >> 8;
    const size_t tile_base = (((size_t)dir * Sn + s) * 64 + blk) * 1024;
    float bx = bias[n + 0], by = bias[n + 1], bz = bias[n + 2], bw = bias[n + 3];
#pragma unroll
    for (int c = 0; c < 4; c++) {
        const int b = 4 * tm + c;
        float4 v;
        v.x = acc[c][0] + bx; v.y = acc[c][1] + by;
        v.z = acc[c][2] + bz; v.w = acc[c][3] + bw;
        *reinterpret_cast<float4*>(&g_Xperm[tile_base + (size_t)b * 16 + mg * 4]) = v;
    }
}

// ---------------------------------------------------------------------------
// Flag-array grid barrier (per direction, 64 blocks).
// Each block writes a monotonic counter to its OWN slot (no atomic
// contention); threads 0..63 each poll one slot with a wrap-safe signed
// compare. `target` is base + n where base is read at kernel start.
// ---------------------------------------------------------------------------
__device__ __forceinline__ void flag_barrier(int dir, int blk, unsigned target) {
    __threadfence();                 // publish this thread's global writes
    __syncthreads();                 // all threads' writes issued + fenced
    const int tid = threadIdx.x;
    if (tid == 0) g_arrive[dir][blk] = target;
    if (tid < 64) {
        while ((int)(g_arrive[dir][tid] - target) < 0) { }
    }
    __syncthreads();
}

// ---------------------------------------------------------------------------
// Kernel 2: persistent bidirectional LSTM recurrence (dynamic smem, 88 KB).
// 128 blocks (64/dir), 256 threads. Block (dir,blk) owns gate rows
// {m*256 + blk*4 + r}. Per step: full h (64KB) loaded via cp.async (deep
// MLP, single wait), one compute pass, flag barrier.
// Dynamic smem layout (floats):
//   [0, 4096)            sW[16][256]
//   [4096, 4096+16640)   sh[64][260]
//   [20736, 20736+1088)  sG[64][17]
//   [21824, 21824+256)   sC[64][4]
// ---------------------------------------------------------------------------
#define SH_STRIDE 260
__global__ void __launch_bounds__(256, 1)
lstm_recur_kernel(const float* __restrict__ Whh_f,
                  const float* __restrict__ Whh_b) {
    extern __shared__ float smem[];
    float* sW = smem;                        // [16][256]
    float* sh = smem + 4096;                 // [64][260]
    float* sG = smem + 4096 + 64 * SH_STRIDE;// [64][17]
    float* sC = sG + 64 * 17;                // [64][4]

    const int dir = blockIdx.x >> 6;
    const int blk = blockIdx.x & 63;
    const float* __restrict__ Whh = dir ? Whh_b : Whh_f;

    const int tid = threadIdx.x;

    // Launch-reentrant barrier base: own slot, written only by this block.
    const unsigned base = g_arrive[dir][blk];

    for (int i = tid; i < 4096; i += 256) {
        int jl = i >> 8, k = i & 255;
        sW[jl * 256 + k] = Whh[(size_t)(((jl >> 2) << 8) + (blk << 2) + (jl & 3)) * Hn + k];
    }
    {
        sC[tid] = 0.0f;
        g_hstate[0][dir][blk * 256 + tid] = 0.0f;
    }
    flag_barrier(dir, blk, base + 1);

    // compute mapping: warp w handles j = 4*(w&3).., batches (w>>2)*32 + lane
    const int jq4 = ((tid >> 5) & 3) * 4;
    const int bh = ((tid >> 7) << 5) + (tid & 31);
    // update mapping
    const int ub = tid >> 2, ur = tid & 3;
    // loader mapping: row = tid>>2, col base = (tid&3)*64 (16 float4 each)
    const int lr = tid >> 2;
    const int lc = (tid & 3) * 64;
    const uint32_t sh_dst = (uint32_t)__cvta_generic_to_shared(&sh[lr * SH_STRIDE + lc]);

    // prefetch X for step 0
    const int s_first = dir ? 511 : 0;
    float4 xv = *reinterpret_cast<const float4*>(
        &g_Xperm[(((size_t)dir * Sn + s_first) * 64 + blk) * 1024 + tid * 4]);

    for (int step = 0; step < 512; step++) {
        const int s = dir ? (511 - step) : step;
        const int par = step & 1;
        const float* __restrict__ hin = g_hstate[par][dir];
        float* __restrict__ hout = g_hstate[par ^ 1][dir];

        // deposit prefetched X tile into sG (gate accumulator base)
        {
            int bb = tid >> 2, jl = (tid & 3) * 4;
            sG[bb * 17 + jl + 0] = xv.x; sG[bb * 17 + jl + 1] = xv.y;
            sG[bb * 17 + jl + 2] = xv.z; sG[bb * 17 + jl + 3] = xv.w;
        }

        // issue all h loads (16 cp.async per thread, 64KB total)
        {
            const float* gsrc = &hin[lr * 256 + lc];
#pragma unroll
            for (int i = 0; i < 16; i++) {
                cp_async16(sh_dst + i * 16, gsrc + i * 4);
            }
            asm volatile("cp.async.commit_group;");
        }

        // prefetch X for next step (latency hidden behind the cp.async wait)
        if (step < 511) {
            const int sn = dir ? (510 - step) : (step + 1);
            xv = *reinterpret_cast<const float4*>(
                &g_Xperm[(((size_t)dir * Sn + sn) * 64 + blk) * 1024 + tid * 4]);
        }

        asm volatile("cp.async.wait_group 0;");
        __syncthreads();

        // dot products: 4 j-rows x 256 k per thread
        float a0 = 0.f, a1 = 0.f, a2 = 0.f, a3 = 0.f;
        const float* shrow = &sh[bh * SH_STRIDE];
        const float* w0p = &sW[(jq4 + 0) * 256];
        const float* w1p = &sW[(jq4 + 1) * 256];
        const float* w2p = &sW[(jq4 + 2) * 256];
        const float* w3p = &sW[(jq4 + 3) * 256];
#pragma unroll 8
        for (int kk = 0; kk < 64; kk++) {
            float4 h  = *reinterpret_cast<const float4*>(&shrow[kk * 4]);
            float4 w0 = *reinterpret_cast<const float4*>(&w0p[kk * 4]);
            float4 w1 = *reinterpret_cast<const float4*>(&w1p[kk * 4]);
            float4 w2 = *reinterpret_cast<const float4*>(&w2p[kk * 4]);
            float4 w3 = *reinterpret_cast<const float4*>(&w3p[kk * 4]);
            a0 += h.x * w0.x + h.y * w0.y + h.z * w0.z + h.w * w0.w;
            a1 += h.x * w1.x + h.y * w1.y + h.z * w1.z + h.w * w1.w;
            a2 += h.x * w2.x + h.y * w2.y + h.z * w2.z + h.w * w2.w;
            a3 += h.x * w3.x + h.y * w3.y + h.z * w3.z + h.w * w3.w;
        }
        sG[bh * 17 + jq4 + 0] += a0;
        sG[bh * 17 + jq4 + 1] += a1;
        sG[bh * 17 + jq4 + 2] += a2;
        sG[bh * 17 + jq4 + 3] += a3;
        __syncthreads();

        // pointwise LSTM cell update
        {
            float gi = sG[ub * 17 + 0 + ur];
            float gf = sG[ub * 17 + 4 + ur];
            float gg = sG[ub * 17 + 8 + ur];
            float go = sG[ub * 17 + 12 + ur];
            float c = sC[ub * 4 + ur];
            c = fsig(gf) * c + fsig(gi) * ftanh(gg);
            float h = fsig(go) * ftanh(c);
            sC[ub * 4 + ur] = c;
            const int hcol = (blk << 2) + ur;
            hout[ub * 256 + hcol] = h;
            g_Hbuf[(((size_t)dir * Sn + s) * Bn + ub) * Hn + hcol] = h;
        }
        flag_barrier(dir, blk, base + 2 + step);
    }
}

// ---------------------------------------------------------------------------
// Kernel 3: emissions em[b][s][l] = [hf,hb] @ Wo + bo. One warp per (s,b).
// ---------------------------------------------------------------------------
__global__ void emissions_kernel(const float* __restrict__ Wo,
                                 const float* __restrict__ bo) {
    const int warp = (blockIdx.x * blockDim.x + threadIdx.x) >> 5;
    const int lane = threadIdx.x & 31;
    if (warp >= Bn * Sn) return;
    const int s = warp >> 6;
    const int b = warp & 63;
    const float* __restrict__ hf = &g_Hbuf[(((size_t)0 * Sn + s) * Bn + b) * Hn];
    const float* __restrict__ hb = &g_Hbuf[(((size_t)1 * Sn + s) * Bn + b) * Hn];

    float acc[9];
#pragma unroll
    for (int j = 0; j < 9; j++) acc[j] = 0.0f;

    for (int k = lane; k < 256; k += 32) {
        float vf = hf[k];
        float vb = hb[k];
        const float* w1 = &Wo[(size_t)k * Ln];
        const float* w2 = &Wo[(size_t)(256 + k) * Ln];
#pragma unroll
        for (int j = 0; j < 9; j++) acc[j] += vf * w1[j] + vb * w2[j];
    }
#pragma unroll
    for (int j = 0; j < 9; j++) {
        float v = acc[j];
#pragma unroll
        for (int o = 16; o; o >>= 1) v += __shfl_down_sync(0xffffffffu, v, o);
        if (lane == 0) g_em[((size_t)b * Sn + s) * Ln + j] = v + bo[j];
    }
}

// ---------------------------------------------------------------------------
// Kernel 4: CRF forward (register alpha + shfl broadcast, em prefetch) and
// gold score (t-parallel). One warp per batch.
// ---------------------------------------------------------------------------
__global__ void crf_kernel(const int* __restrict__ x,
                           const int* __restrict__ y,
                           const float* __restrict__ T,
                           const float* __restrict__ start,
                           const float* __restrict__ end) {
    const int b = blockIdx.x;
    const int lane = threadIdx.x;
    const float* __restrict__ em = &g_em[(size_t)b * Sn * Ln];
    const int* __restrict__ xb = &x[b * Sn];
    const int* __restrict__ yb = &y[b * Sn];
    const bool act = lane < 9;

    float Tcol[9];
    if (act) {
#pragma unroll
        for (int i = 0; i < 9; i++) Tcol[i] = T[i * 9 + lane];
    }
    float alpha = act ? (start[lane] + em[lane]) : -1e30f;

    // prefetched state for step t
    int xt = __ldg(&xb[1]);
    float emt = act ? __ldg(&em[Ln + lane]) : 0.0f;

    for (int t = 1; t < Sn; t++) {
        // issue next-step loads first (hide L2 latency behind the lse chain)
        int xt_n = 0;
        float emt_n = 0.0f;
        if (t + 1 < Sn) {
            xt_n = __ldg(&xb[t + 1]);
            if (act) emt_n = __ldg(&em[(t + 1) * Ln + lane]);
        }

        float ai[9];
#pragma unroll
        for (int i = 0; i < 9; i++) ai[i] = __shfl_sync(0xffffffffu, alpha, i);
        if (xt != 0) {
            float v[9];
#pragma unroll
            for (int i = 0; i < 9; i++) v[i] = ai[i] + Tcol[i];
            float m01 = fmaxf(v[0], v[1]), m23 = fmaxf(v[2], v[3]);
            float m45 = fmaxf(v[4], v[5]), m67 = fmaxf(v[6], v[7]);
            float mx = fmaxf(fmaxf(fmaxf(m01, m23), fmaxf(m45, m67)), v[8]);
            float ssum = 0.0f;
#pragma unroll
            for (int i = 0; i < 9; i++) ssum += __expf(v[i] - mx);
            float na = mx + __logf(ssum) + emt;
            if (act) alpha = na;
        }
        xt = xt_n;
        emt = emt_n;
    }

    // logZ = logsumexp over 9 labels
    float vz = act ? (alpha + end[lane]) : -1e30f;
    float mx = vz;
#pragma unroll
    for (int o = 16; o; o >>= 1) mx = fmaxf(mx, __shfl_xor_sync(0xffffffffu, mx, o));
    float e = act ? __expf(vz - mx) : 0.0f;
#pragma unroll
    for (int o = 16; o; o >>= 1) e += __shfl_xor_sync(0xffffffffu, e, o);
    float logZ = mx + __logf(e);

    // gold score: t-parallel (prev label is y[t-1], no carried dependency)
    float gs = 0.0f;
    int cnt = 0;
    for (int t = lane; t < Sn; t += 32) {
        int m = (__ldg(&xb[t]) != 0) ? 1 : 0;
        cnt += m;
        if (t >= 1 && m) {
            int yt = __ldg(&yb[t]);
            int yp = __ldg(&yb[t - 1]);
            gs += T[yp * 9 + yt] + em[t * Ln + yt];
        }
    }
#pragma unroll
    for (int o = 16; o; o >>= 1) {
        gs  += __shfl_xor_sync(0xffffffffu, gs, o);
        cnt += __shfl_xor_sync(0xffffffffu, cnt, o);
    }

    if (lane == 0) {
        int y0 = yb[0];
        float score = start[y0] + em[y0] + gs;
        int last = cnt - 1;
        if (last < 0) last = 0;
        score += end[yb[last]];
        g_res[b] = logZ - score;
    }
}

// ---------------------------------------------------------------------------
// Kernel 5: mean over batch -> scalar output
// ---------------------------------------------------------------------------
__global__ void reduce_kernel(float* __restrict__ out) {
    __shared__ float s[64];
    s[threadIdx.x] = g_res[threadIdx.x];
    __syncthreads();
    if (threadIdx.x == 0) {
        float t = 0.0f;
        for (int i = 0; i < 64; i++) t += s[i];
        out[0] = t * (1.0f / 64.0f);
    }
}

// ---------------------------------------------------------------------------
extern "C" void kernel_launch(void* const* d_in, const int* in_sizes, int n_in,
                              void* d_out, int out_size) {
    const int*   x      = (const int*)  d_in[0];
    const int*   y      = (const int*)  d_in[1];
    const float* E      = (const float*)d_in[2];
    const float* Wih_f  = (const float*)d_in[3];
    const float* Whh_f  = (const float*)d_in[4];
    const float* b_f    = (const float*)d_in[5];
    const float* Wih_b  = (const float*)d_in[6];
    const float* Whh_b  = (const float*)d_in[7];
    const float* b_b    = (const float*)d_in[8];
    const float* Wo     = (const float*)d_in[9];
    const float* bo     = (const float*)d_in[10];
    const float* T      = (const float*)d_in[11];
    const float* start  = (const float*)d_in[12];
    const float* end    = (const float*)d_in[13];
    float* out = (float*)d_out;

    // Dynamic smem for the recurrence kernel: sW 16KB + sh 65KB + sG + sC
    const int recur_smem = (4096 + 64 * SH_STRIDE + 64 * 17 + 256) * (int)sizeof(float);
    cudaFuncSetAttribute(lstm_recur_kernel,
                         cudaFuncAttributeMaxDynamicSharedMemorySize, recur_smem);

    dim3 gemm_grid(16, 512, 2);
    embed_inproj_kernel<<<gemm_grid, 256>>>(x, E, Wih_f, b_f, Wih_b, b_b);
    lstm_recur_kernel<<<128, 256, recur_smem>>>(Whh_f, Whh_b);
    emissions_kernel<<<4096, 256>>>(Wo, bo);
    crf_kernel<<<64, 32>>>(x, y, T, start, end);
    reduce_kernel<<<1, 64>>>(out);
}

// round 7
// speedup vs baseline: 1.8756x; 1.8756x over previous
#include <cuda_runtime.h>
#include <cuda_bf16.h>
#include <cstdint>

// Problem constants
#define Bn 64
#define Sn 512
#define Dn 256
#define Hn 256
#define Ln 9

// ---------------------------------------------------------------------------
// Static device scratch
// ---------------------------------------------------------------------------
__device__ float g_Xperm[2u * 512u * 64u * 1024u];      // 268 MB
__device__ float g_Hbuf[2u * 512u * 64u * 256u];        // 67 MB
__device__ float g_hstate[2][2][Bn * Hn];               // [parity][dir]
__device__ float g_em[(size_t)Bn * Sn * Ln];
__device__ float g_res[Bn];
// Split barrier counters: 8 per direction, each on its own 128B line.
__device__ unsigned g_cnt[2][8][32];
__device__ unsigned g_exit[2];

__device__ __forceinline__ float fsig(float x) { return 1.0f / (1.0f + __expf(-x)); }
__device__ __forceinline__ float ftanh(float x) { return 2.0f / (1.0f + __expf(-2.0f * x)) - 1.0f; }

// ---------------------------------------------------------------------------
// Kernel 1: embedding gather + input projection GEMM (+bias), permuted write.
// ---------------------------------------------------------------------------
__global__ void embed_inproj_kernel(const int* __restrict__ x,
                                    const float* __restrict__ E,
                                    const float* __restrict__ Wih_f,
                                    const float* __restrict__ b_f,
                                    const float* __restrict__ Wih_b,
                                    const float* __restrict__ b_b) {
    const int dir = blockIdx.z;
    const float* __restrict__ W = dir ? Wih_b : Wih_f;
    const float* __restrict__ bias = dir ? b_b : b_f;
    const int s = blockIdx.y;
    const int n0 = blockIdx.x * 64;

    __shared__ float sA[16][68];
    __shared__ float sB[16][68];
    __shared__ int srow[64];

    const int tid = threadIdx.x;
    if (tid < 64) srow[tid] = x[tid * Sn + s];
    __syncthreads();

    const int tm = tid & 15;
    const int tn = tid >> 4;
    const int lrow = tid >> 2;
    const int kq = tid & 3;

    float acc[4][4];
#pragma unroll
    for (int c = 0; c < 4; c++)
#pragma unroll
        for (int d = 0; d < 4; d++) acc[c][d] = 0.0f;

    for (int k0 = 0; k0 < 256; k0 += 16) {
        float4 a4 = *reinterpret_cast<const float4*>(&E[(size_t)srow[lrow] * Dn + k0 + kq * 4]);
        float4 b4 = *reinterpret_cast<const float4*>(&W[(size_t)(n0 + lrow) * Dn + k0 + kq * 4]);
        __syncthreads();
        sA[kq * 4 + 0][lrow] = a4.x; sA[kq * 4 + 1][lrow] = a4.y;
        sA[kq * 4 + 2][lrow] = a4.z; sA[kq * 4 + 3][lrow] = a4.w;
        sB[kq * 4 + 0][lrow] = b4.x; sB[kq * 4 + 1][lrow] = b4.y;
        sB[kq * 4 + 2][lrow] = b4.z; sB[kq * 4 + 3][lrow] = b4.w;
        __syncthreads();
#pragma unroll
        for (int kk = 0; kk < 16; kk++) {
            float4 ra = *reinterpret_cast<float4*>(&sA[kk][4 * tm]);
            float4 rb = *reinterpret_cast<float4*>(&sB[kk][4 * tn]);
            acc[0][0] += ra.x * rb.x; acc[0][1] += ra.x * rb.y; acc[0][2] += ra.x * rb.z; acc[0][3] += ra.x * rb.w;
            acc[1][0] += ra.y * rb.x; acc[1][1] += ra.y * rb.y; acc[1][2] += ra.y * rb.z; acc[1][3] += ra.y * rb.w;
            acc[2][0] += ra.z * rb.x; acc[2][1] += ra.z * rb.y; acc[2][2] += ra.z * rb.z; acc[2][3] += ra.z * rb.w;
            acc[3][0] += ra.w * rb.x; acc[3][1] += ra.w * rb.y; acc[3][2] += ra.w * rb.z; acc[3][3] += ra.w * rb.w;
        }
    }

    const int n = n0 + 4 * tn;
    const int blk = (n & 255) >> 2;
    const int mg = n >> 8;
    const size_t tile_base = (((size_t)dir * Sn + s) * 64 + blk) * 1024;
    float bx = bias[n + 0], by = bias[n + 1], bz = bias[n + 2], bw = bias[n + 3];
#pragma unroll
    for (int c = 0; c < 4; c++) {
        const int b = 4 * tm + c;
        float4 v;
        v.x = acc[c][0] + bx; v.y = acc[c][1] + by;
        v.z = acc[c][2] + bz; v.w = acc[c][3] + bw;
        *reinterpret_cast<float4*>(&g_Xperm[tile_base + (size_t)b * 16 + mg * 4]) = v;
    }
}

// ---------------------------------------------------------------------------
// Split-counter grid barrier (per direction, 64 blocks).
// Arrival: atomicAdd to counter (blk & 7) — 8-way parallel arrival, each
// counter serializes only 8 atomics. Wait: threads 0..7 each poll one
// padded counter line (64 readers per line, same contention level as the
// proven R4 barrier) until it reaches 8*n. Counters are monotonic within a
// launch (n = barrier ordinal); the last block to exit resets them so the
// next graph replay starts from zero.
// ---------------------------------------------------------------------------
__device__ __forceinline__ void dir_barrier(int dir, int blk, unsigned n) {
    __threadfence();                 // publish this thread's global writes
    __syncthreads();                 // all threads' writes issued + fenced
    const int tid = threadIdx.x;
    if (tid == 0) atomicAdd(&g_cnt[dir][blk & 7][0], 1u);
    if (tid < 8) {
        const unsigned tgt = n * 8u;
        volatile unsigned* p = &g_cnt[dir][tid][0];
        while ((int)(*p - tgt) < 0) { }
    }
    __syncthreads();
}

// ---------------------------------------------------------------------------
// Kernel 2: persistent bidirectional LSTM recurrence (R4-proven body).
// 128 blocks (64/dir), 256 threads. Block (dir,blk) owns gate rows
// {m*256 + blk*4 + r}. Chunked pipelined h loads (registers double-buffer),
// X(s+1) prefetched under the last chunk. Barrier per step except the last.
// ---------------------------------------------------------------------------
__global__ void lstm_recur_kernel(const float* __restrict__ Whh_f,
                                  const float* __restrict__ Whh_b) {
    const int dir = blockIdx.x >> 6;
    const int blk = blockIdx.x & 63;
    const float* __restrict__ Whh = dir ? Whh_b : Whh_f;

    __shared__ float sW[16][256];   // 16 KB stationary weights
    __shared__ float sh[64][68];    // h chunk (pad: conflict-free LDS.128)
    __shared__ float sG[64][17];    // gates
    __shared__ float sC[64][4];     // cell state

    const int tid = threadIdx.x;

    for (int i = tid; i < 4096; i += 256) {
        int jl = i >> 8, k = i & 255;
        sW[jl][k] = Whh[(size_t)(((jl >> 2) << 8) + (blk << 2) + (jl & 3)) * Hn + k];
    }
    {
        int ub0 = tid >> 2, ur0 = tid & 3;
        sC[ub0][ur0] = 0.0f;
        g_hstate[0][dir][blk * 256 + tid] = 0.0f;
    }
    dir_barrier(dir, blk, 1u);

    // compute mapping: warp w handles j = 4*(w&3).., batches (w>>2)*32 + lane
    const int jq4 = ((tid >> 5) & 3) * 4;
    const int bh = ((tid >> 7) << 5) + (tid & 31);
    // update mapping
    const int ub = tid >> 2, ur = tid & 3;
    // loader mapping (4 float4 per thread per chunk)
    const int lb0 = tid >> 4;             const int lk0 = (tid & 15) * 4;
    const int lb1 = (tid + 256) >> 4;
    const int lb2 = (tid + 512) >> 4;
    const int lb3 = (tid + 768) >> 4;

    // prefetch X for step 0
    const int s_first = dir ? 511 : 0;
    float4 xv = *reinterpret_cast<const float4*>(
        &g_Xperm[(((size_t)dir * Sn + s_first) * 64 + blk) * 1024 + tid * 4]);

    for (int step = 0; step < 512; step++) {
        const int s = dir ? (511 - step) : step;
        const int par = step & 1;
        const float* __restrict__ hin = g_hstate[par][dir];
        float* __restrict__ hout = g_hstate[par ^ 1][dir];

        // deposit prefetched X tile into sG (gate accumulator base)
        {
            int bb = tid >> 2, jl = (tid & 3) * 4;
            sG[bb][jl + 0] = xv.x; sG[bb][jl + 1] = xv.y;
            sG[bb][jl + 2] = xv.z; sG[bb][jl + 3] = xv.w;
        }

        // issue h chunk-0 loads
        float4 r0 = __ldcg(reinterpret_cast<const float4*>(&hin[lb0 * 256 + 0 + lk0]));
        float4 r1 = __ldcg(reinterpret_cast<const float4*>(&hin[lb1 * 256 + 0 + lk0]));
        float4 r2 = __ldcg(reinterpret_cast<const float4*>(&hin[lb2 * 256 + 0 + lk0]));
        float4 r3 = __ldcg(reinterpret_cast<const float4*>(&hin[lb3 * 256 + 0 + lk0]));

        float a0 = 0.f, a1 = 0.f, a2 = 0.f, a3 = 0.f;
#pragma unroll
        for (int kc = 0; kc < 4; kc++) {
            // deposit regs into sh
            *reinterpret_cast<float4*>(&sh[lb0][lk0]) = r0;
            *reinterpret_cast<float4*>(&sh[lb1][lk0]) = r1;
            *reinterpret_cast<float4*>(&sh[lb2][lk0]) = r2;
            *reinterpret_cast<float4*>(&sh[lb3][lk0]) = r3;
            __syncthreads();
            const int kb = kc << 6;
            if (kc < 3) {
                const int kn = kb + 64;
                r0 = __ldcg(reinterpret_cast<const float4*>(&hin[lb0 * 256 + kn + lk0]));
                r1 = __ldcg(reinterpret_cast<const float4*>(&hin[lb1 * 256 + kn + lk0]));
                r2 = __ldcg(reinterpret_cast<const float4*>(&hin[lb2 * 256 + kn + lk0]));
                r3 = __ldcg(reinterpret_cast<const float4*>(&hin[lb3 * 256 + kn + lk0]));
            } else if (step < 511) {
                const int sn = dir ? (510 - step) : (step + 1);
                xv = *reinterpret_cast<const float4*>(
                    &g_Xperm[(((size_t)dir * Sn + sn) * 64 + blk) * 1024 + tid * 4]);
            }
#pragma unroll
            for (int kk = 0; kk < 16; kk++) {
                float4 h  = *reinterpret_cast<const float4*>(&sh[bh][kk * 4]);
                float4 w0 = *reinterpret_cast<const float4*>(&sW[jq4 + 0][kb + kk * 4]);
                float4 w1 = *reinterpret_cast<const float4*>(&sW[jq4 + 1][kb + kk * 4]);
                float4 w2 = *reinterpret_cast<const float4*>(&sW[jq4 + 2][kb + kk * 4]);
                float4 w3 = *reinterpret_cast<const float4*>(&sW[jq4 + 3][kb + kk * 4]);
                a0 += h.x * w0.x + h.y * w0.y + h.z * w0.z + h.w * w0.w;
                a1 += h.x * w1.x + h.y * w1.y + h.z * w1.z + h.w * w1.w;
                a2 += h.x * w2.x + h.y * w2.y + h.z * w2.z + h.w * w2.w;
                a3 += h.x * w3.x + h.y * w3.y + h.z * w3.z + h.w * w3.w;
            }
            __syncthreads();
        }
        // epilogue: accumulate into gates (distinct (b,j) per thread)
        sG[bh][jq4 + 0] += a0;
        sG[bh][jq4 + 1] += a1;
        sG[bh][jq4 + 2] += a2;
        sG[bh][jq4 + 3] += a3;
        __syncthreads();

        // pointwise LSTM cell update
        {
            float gi = sG[ub][0 + ur];
            float gf = sG[ub][4 + ur];
            float gg = sG[ub][8 + ur];
            float go = sG[ub][12 + ur];
            float c = sC[ub][ur];
            c = fsig(gf) * c + fsig(gi) * ftanh(gg);
            float h = fsig(go) * ftanh(c);
            sC[ub][ur] = c;
            const int hcol = (blk << 2) + ur;
            hout[ub * 256 + hcol] = h;
            g_Hbuf[(((size_t)dir * Sn + s) * Bn + ub) * Hn + hcol] = h;
        }
        // last step needs no cross-block publication (kernel boundary orders it)
        if (step < 511) dir_barrier(dir, blk, 2u + (unsigned)step);
    }

    // Reset barrier counters for the next launch: last block out does it.
    __syncthreads();
    if (tid == 0) {
        unsigned e = atomicAdd(&g_exit[dir], 1u);
        if (e == 63u) {
#pragma unroll
            for (int i = 0; i < 8; i++) g_cnt[dir][i][0] = 0u;
            g_exit[dir] = 0u;
        }
    }
}

// ---------------------------------------------------------------------------
// Kernel 3: emissions em[b][s][l] = [hf,hb] @ Wo + bo. One warp per (s,b).
// ---------------------------------------------------------------------------
__global__ void emissions_kernel(const float* __restrict__ Wo,
                                 const float* __restrict__ bo) {
    const int warp = (blockIdx.x * blockDim.x + threadIdx.x) >> 5;
    const int lane = threadIdx.x & 31;
    if (warp >= Bn * Sn) return;
    const int s = warp >> 6;
    const int b = warp & 63;
    const float* __restrict__ hf = &g_Hbuf[(((size_t)0 * Sn + s) * Bn + b) * Hn];
    const float* __restrict__ hb = &g_Hbuf[(((size_t)1 * Sn + s) * Bn + b) * Hn];

    float acc[9];
#pragma unroll
    for (int j = 0; j < 9; j++) acc[j] = 0.0f;

    for (int k = lane; k < 256; k += 32) {
        float vf = hf[k];
        float vb = hb[k];
        const float* w1 = &Wo[(size_t)k * Ln];
        const float* w2 = &Wo[(size_t)(256 + k) * Ln];
#pragma unroll
        for (int j = 0; j < 9; j++) acc[j] += vf * w1[j] + vb * w2[j];
    }
#pragma unroll
    for (int j = 0; j < 9; j++) {
        float v = acc[j];
#pragma unroll
        for (int o = 16; o; o >>= 1) v += __shfl_down_sync(0xffffffffu, v, o);
        if (lane == 0) g_em[((size_t)b * Sn + s) * Ln + j] = v + bo[j];
    }
}

// ---------------------------------------------------------------------------
// Kernel 4: CRF forward (register alpha + shfl broadcast) and gold score
// (t-parallel). One warp per batch.  (R4-proven version.)
// ---------------------------------------------------------------------------
__global__ void crf_kernel(const int* __restrict__ x,
                           const int* __restrict__ y,
                           const float* __restrict__ T,
                           const float* __restrict__ start,
                           const float* __restrict__ end) {
    const int b = blockIdx.x;
    const int lane = threadIdx.x;
    const float* __restrict__ em = &g_em[(size_t)b * Sn * Ln];
    const int* __restrict__ xb = &x[b * Sn];
    const int* __restrict__ yb = &y[b * Sn];
    const bool act = lane < 9;

    float Tcol[9];
    if (act) {
#pragma unroll
        for (int i = 0; i < 9; i++) Tcol[i] = T[i * 9 + lane];
    }
    float alpha = act ? (start[lane] + em[lane]) : -1e30f;

    for (int t = 1; t < Sn; t++) {
        int xt = __ldg(&xb[t]);
        float emt = act ? __ldg(&em[t * Ln + lane]) : 0.0f;
        float ai[9];
#pragma unroll
        for (int i = 0; i < 9; i++) ai[i] = __shfl_sync(0xffffffffu, alpha, i);
        if (xt != 0) {
            float v[9];
#pragma unroll
            for (int i = 0; i < 9; i++) v[i] = ai[i] + Tcol[i];
            float m01 = fmaxf(v[0], v[1]), m23 = fmaxf(v[2], v[3]);
            float m45 = fmaxf(v[4], v[5]), m67 = fmaxf(v[6], v[7]);
            float mx = fmaxf(fmaxf(fmaxf(m01, m23), fmaxf(m45, m67)), v[8]);
            float ssum = 0.0f;
#pragma unroll
            for (int i = 0; i < 9; i++) ssum += __expf(v[i] - mx);
            float na = mx + __logf(ssum) + emt;
            if (act) alpha = na;
        }
    }

    // logZ = logsumexp over 9 labels
    float vz = act ? (alpha + end[lane]) : -1e30f;
    float mx = vz;
#pragma unroll
    for (int o = 16; o; o >>= 1) mx = fmaxf(mx, __shfl_xor_sync(0xffffffffu, mx, o));
    float e = act ? __expf(vz - mx) : 0.0f;
#pragma unroll
    for (int o = 16; o; o >>= 1) e += __shfl_xor_sync(0xffffffffu, e, o);
    float logZ = mx + __logf(e);

    // gold score: t-parallel (prev label is y[t-1], no carried dependency)
    float gs = 0.0f;
    int cnt = 0;
    for (int t = lane; t < Sn; t += 32) {
        int m = (__ldg(&xb[t]) != 0) ? 1 : 0;
        cnt += m;
        if (t >= 1 && m) {
            int yt = __ldg(&yb[t]);
            int yp = __ldg(&yb[t - 1]);
            gs += T[yp * 9 + yt] + em[t * Ln + yt];
        }
    }
#pragma unroll
    for (int o = 16; o; o >>= 1) {
        gs  += __shfl_xor_sync(0xffffffffu, gs, o);
        cnt += __shfl_xor_sync(0xffffffffu, cnt, o);
    }

    if (lane == 0) {
        int y0 = yb[0];
        float score = start[y0] + em[y0] + gs;
        int last = cnt - 1;
        if (last < 0) last = 0;
        score += end[yb[last]];
        g_res[b] = logZ - score;
    }
}

// ---------------------------------------------------------------------------
// Kernel 5: mean over batch -> scalar output
// ---------------------------------------------------------------------------
__global__ void reduce_kernel(float* __restrict__ out) {
    __shared__ float s[64];
    s[threadIdx.x] = g_res[threadIdx.x];
    __syncthreads();
    if (threadIdx.x == 0) {
        float t = 0.0f;
        for (int i = 0; i < 64; i++) t += s[i];
        out[0] = t * (1.0f / 64.0f);
    }
}

// ---------------------------------------------------------------------------
extern "C" void kernel_launch(void* const* d_in, const int* in_sizes, int n_in,
                              void* d_out, int out_size) {
    const int*   x      = (const int*)  d_in[0];
    const int*   y      = (const int*)  d_in[1];
    const float* E      = (const float*)d_in[2];
    const float* Wih_f  = (const float*)d_in[3];
    const float* Whh_f  = (const float*)d_in[4];
    const float* b_f    = (const float*)d_in[5];
    const float* Wih_b  = (const float*)d_in[6];
    const float* Whh_b  = (const float*)d_in[7];
    const float* b_b    = (const float*)d_in[8];
    const float* Wo     = (const float*)d_in[9];
    const float* bo     = (const float*)d_in[10];
    const float* T      = (const float*)d_in[11];
    const float* start  = (const float*)d_in[12];
    const float* end    = (const float*)d_in[13];
    float* out = (float*)d_out;

    dim3 gemm_grid(16, 512, 2);
    embed_inproj_kernel<<<gemm_grid, 256>>>(x, E, Wih_f, b_f, Wih_b, b_b);
    lstm_recur_kernel<<<128, 256>>>(Whh_f, Whh_b);
    emissions_kernel<<<4096, 256>>>(Wo, bo);
    crf_kernel<<<64, 32>>>(x, y, T, start, end);
    reduce_kernel<<<1, 64>>>(out);
}

// round 8
// speedup vs baseline: 1.9869x; 1.0593x over previous
#include <cuda_runtime.h>
#include <cuda_bf16.h>
#include <cstdint>

// Problem constants
#define Bn 64
#define Sn 512
#define Dn 256
#define Hn 256
#define Ln 9

// ---------------------------------------------------------------------------
// Static device scratch
// ---------------------------------------------------------------------------
__device__ float g_Xperm[2u * 512u * 64u * 1024u];      // 268 MB
__device__ float g_Hbuf[2u * 512u * 64u * 256u];        // 67 MB
__device__ float g_hstate[2][2][Bn * Hn];               // [parity][dir]
__device__ float g_em[(size_t)Bn * Sn * Ln];
__device__ float g_res[Bn];
// Split barrier counters: 8 per direction, each on its own 128B line.
__device__ unsigned g_cnt[2][8][32];
__device__ unsigned g_exit[2];

__device__ __forceinline__ float fsig(float x) { return 1.0f / (1.0f + __expf(-x)); }
__device__ __forceinline__ float ftanh(float x) { return 2.0f / (1.0f + __expf(-2.0f * x)) - 1.0f; }

// Packed f32x2 FMA (sm_100+): d = a*b + d, lane-wise on 2 packed floats.
__device__ __forceinline__ void ffma2(unsigned long long& d,
                                      unsigned long long a,
                                      unsigned long long b) {
    asm("fma.rn.f32x2 %0, %1, %2, %0;" : "+l"(d) : "l"(a), "l"(b));
}
__device__ __forceinline__ unsigned long long dup2(float x) {
    unsigned long long r;
    asm("mov.b64 %0, {%1, %1};" : "=l"(r) : "f"(x));
    return r;
}
__device__ __forceinline__ float hsum2(unsigned long long p) {
    float lo, hi;
    asm("mov.b64 {%0, %1}, %2;" : "=f"(lo), "=f"(hi) : "l"(p));
    return lo + hi;
}

// ---------------------------------------------------------------------------
// Kernel 1: embedding gather + input projection GEMM (+bias), permuted write.
// Tile 64m x 128n, K-chunk 16, 256 threads, 4x8 micro-tile, packed FFMA2.
// grid = (8 n-tiles, 512 s, 2 dirs)
// ---------------------------------------------------------------------------
__global__ void embed_inproj_kernel(const int* __restrict__ x,
                                    const float* __restrict__ E,
                                    const float* __restrict__ Wih_f,
                                    const float* __restrict__ b_f,
                                    const float* __restrict__ Wih_b,
                                    const float* __restrict__ b_b) {
    const int dir = blockIdx.z;
    const float* __restrict__ W = dir ? Wih_b : Wih_f;
    const float* __restrict__ bias = dir ? b_b : b_f;
    const int s = blockIdx.y;
    const int n0 = blockIdx.x * 128;

    __shared__ float sA[16][68];     // A^T: [k][m], 64 m + pad
    __shared__ float sB[16][132];    // B^T: [k][n], 128 n + pad
    __shared__ int srow[64];

    const int tid = threadIdx.x;
    if (tid < 64) srow[tid] = x[tid * Sn + s];
    __syncthreads();

    const int tm = tid & 15;          // 4 m-rows: 4*tm..
    const int tn = tid >> 4;          // 8 n-cols: 8*tn..
    const int lrow = tid >> 2;        // loader row 0..63
    const int kq = tid & 3;           // loader k-quad

    unsigned long long acc[4][4];     // [m][n-pair], each packs 2 n-values
#pragma unroll
    for (int c = 0; c < 4; c++)
#pragma unroll
        for (int p = 0; p < 4; p++) acc[c][p] = 0ull;

    for (int k0 = 0; k0 < 256; k0 += 16) {
        float4 a4 = *reinterpret_cast<const float4*>(&E[(size_t)srow[lrow] * Dn + k0 + kq * 4]);
        float4 b4 = *reinterpret_cast<const float4*>(&W[(size_t)(n0 + lrow) * Dn + k0 + kq * 4]);
        float4 c4 = *reinterpret_cast<const float4*>(&W[(size_t)(n0 + 64 + lrow) * Dn + k0 + kq * 4]);
        __syncthreads();   // previous compute done reading smem
        sA[kq * 4 + 0][lrow] = a4.x; sA[kq * 4 + 1][lrow] = a4.y;
        sA[kq * 4 + 2][lrow] = a4.z; sA[kq * 4 + 3][lrow] = a4.w;
        sB[kq * 4 + 0][lrow] = b4.x; sB[kq * 4 + 1][lrow] = b4.y;
        sB[kq * 4 + 2][lrow] = b4.z; sB[kq * 4 + 3][lrow] = b4.w;
        sB[kq * 4 + 0][64 + lrow] = c4.x; sB[kq * 4 + 1][64 + lrow] = c4.y;
        sB[kq * 4 + 2][64 + lrow] = c4.z; sB[kq * 4 + 3][64 + lrow] = c4.w;
        __syncthreads();
#pragma unroll
        for (int kk = 0; kk < 16; kk++) {
            float4 ra = *reinterpret_cast<float4*>(&sA[kk][4 * tm]);
            ulonglong2 rb0 = *reinterpret_cast<ulonglong2*>(&sB[kk][8 * tn]);
            ulonglong2 rb1 = *reinterpret_cast<ulonglong2*>(&sB[kk][8 * tn + 4]);
            unsigned long long d0 = dup2(ra.x), d1 = dup2(ra.y);
            unsigned long long d2 = dup2(ra.z), d3 = dup2(ra.w);
            ffma2(acc[0][0], d0, rb0.x); ffma2(acc[0][1], d0, rb0.y);
            ffma2(acc[0][2], d0, rb1.x); ffma2(acc[0][3], d0, rb1.y);
            ffma2(acc[1][0], d1, rb0.x); ffma2(acc[1][1], d1, rb0.y);
            ffma2(acc[1][2], d1, rb1.x); ffma2(acc[1][3], d1, rb1.y);
            ffma2(acc[2][0], d2, rb0.x); ffma2(acc[2][1], d2, rb0.y);
            ffma2(acc[2][2], d2, rb1.x); ffma2(acc[2][3], d2, rb1.y);
            ffma2(acc[3][0], d3, rb0.x); ffma2(acc[3][1], d3, rb0.y);
            ffma2(acc[3][2], d3, rb1.x); ffma2(acc[3][3], d3, rb1.y);
        }
    }

    // Epilogue: add bias, permuted write. n-range: n0 + 8*tn .. +7.
    const int nb = n0 + 8 * tn;                 // 8-aligned gate row base
    // n..n+3 share (blk, mg); n+4..n+7 are the next blk.
    const int blkA = (nb >> 2) & 63;  const int mgA = nb >> 8;
    const int nb2 = nb + 4;
    const int blkB = (nb2 >> 2) & 63; const int mgB = nb2 >> 8;
    const size_t baseA = (((size_t)dir * Sn + s) * 64 + blkA) * 1024 + (size_t)mgA * 4;
    const size_t baseB = (((size_t)dir * Sn + s) * 64 + blkB) * 1024 + (size_t)mgB * 4;
    float4 biasA = *reinterpret_cast<const float4*>(&bias[nb]);
    float4 biasB = *reinterpret_cast<const float4*>(&bias[nb + 4]);
#pragma unroll
    for (int c = 0; c < 4; c++) {
        const int b = 4 * tm + c;
        float f0, f1, f2, f3, f4, f5, f6, f7;
        asm("mov.b64 {%0, %1}, %2;" : "=f"(f0), "=f"(f1) : "l"(acc[c][0]));
        asm("mov.b64 {%0, %1}, %2;" : "=f"(f2), "=f"(f3) : "l"(acc[c][1]));
        asm("mov.b64 {%0, %1}, %2;" : "=f"(f4), "=f"(f5) : "l"(acc[c][2]));
        asm("mov.b64 {%0, %1}, %2;" : "=f"(f6), "=f"(f7) : "l"(acc[c][3]));
        float4 vA, vB;
        vA.x = f0 + biasA.x; vA.y = f1 + biasA.y; vA.z = f2 + biasA.z; vA.w = f3 + biasA.w;
        vB.x = f4 + biasB.x; vB.y = f5 + biasB.y; vB.z = f6 + biasB.z; vB.w = f7 + biasB.w;
        *reinterpret_cast<float4*>(&g_Xperm[baseA + (size_t)b * 16]) = vA;
        *reinterpret_cast<float4*>(&g_Xperm[baseB + (size_t)b * 16]) = vB;
    }
}

// ---------------------------------------------------------------------------
// Split-counter grid barrier (per direction, 64 blocks).
// ---------------------------------------------------------------------------
__device__ __forceinline__ void dir_barrier(int dir, int blk, unsigned n) {
    __threadfence();                 // publish this thread's global writes
    __syncthreads();                 // all threads' writes issued + fenced
    const int tid = threadIdx.x;
    if (tid == 0) atomicAdd(&g_cnt[dir][blk & 7][0], 1u);
    if (tid < 8) {
        const unsigned tgt = n * 8u;
        volatile unsigned* p = &g_cnt[dir][tid][0];
        while ((int)(*p - tgt) < 0) { }
    }
    __syncthreads();
}

// ---------------------------------------------------------------------------
// Kernel 2: persistent bidirectional LSTM recurrence (R7 body + FFMA2 core).
// ---------------------------------------------------------------------------
__global__ void lstm_recur_kernel(const float* __restrict__ Whh_f,
                                  const float* __restrict__ Whh_b) {
    const int dir = blockIdx.x >> 6;
    const int blk = blockIdx.x & 63;
    const float* __restrict__ Whh = dir ? Whh_b : Whh_f;

    __shared__ float sW[16][256];   // 16 KB stationary weights
    __shared__ float sh[64][68];    // h chunk (pad: conflict-free LDS.128)
    __shared__ float sG[64][17];    // gates
    __shared__ float sC[64][4];     // cell state

    const int tid = threadIdx.x;

    for (int i = tid; i < 4096; i += 256) {
        int jl = i >> 8, k = i & 255;
        sW[jl][k] = Whh[(size_t)(((jl >> 2) << 8) + (blk << 2) + (jl & 3)) * Hn + k];
    }
    {
        int ub0 = tid >> 2, ur0 = tid & 3;
        sC[ub0][ur0] = 0.0f;
        g_hstate[0][dir][blk * 256 + tid] = 0.0f;
    }
    dir_barrier(dir, blk, 1u);

    // compute mapping: warp w handles j = 4*(w&3).., batches (w>>2)*32 + lane
    const int jq4 = ((tid >> 5) & 3) * 4;
    const int bh = ((tid >> 7) << 5) + (tid & 31);
    // update mapping
    const int ub = tid >> 2, ur = tid & 3;
    // loader mapping (4 float4 per thread per chunk)
    const int lb0 = tid >> 4;             const int lk0 = (tid & 15) * 4;
    const int lb1 = (tid + 256) >> 4;
    const int lb2 = (tid + 512) >> 4;
    const int lb3 = (tid + 768) >> 4;

    // prefetch X for step 0
    const int s_first = dir ? 511 : 0;
    float4 xv = *reinterpret_cast<const float4*>(
        &g_Xperm[(((size_t)dir * Sn + s_first) * 64 + blk) * 1024 + tid * 4]);

    for (int step = 0; step < 512; step++) {
        const int s = dir ? (511 - step) : step;
        const int par = step & 1;
        const float* __restrict__ hin = g_hstate[par][dir];
        float* __restrict__ hout = g_hstate[par ^ 1][dir];

        // deposit prefetched X tile into sG (gate accumulator base)
        {
            int bb = tid >> 2, jl = (tid & 3) * 4;
            sG[bb][jl + 0] = xv.x; sG[bb][jl + 1] = xv.y;
            sG[bb][jl + 2] = xv.z; sG[bb][jl + 3] = xv.w;
        }

        // issue h chunk-0 loads
        float4 r0 = __ldcg(reinterpret_cast<const float4*>(&hin[lb0 * 256 + 0 + lk0]));
        float4 r1 = __ldcg(reinterpret_cast<const float4*>(&hin[lb1 * 256 + 0 + lk0]));
        float4 r2 = __ldcg(reinterpret_cast<const float4*>(&hin[lb2 * 256 + 0 + lk0]));
        float4 r3 = __ldcg(reinterpret_cast<const float4*>(&hin[lb3 * 256 + 0 + lk0]));

        unsigned long long A0 = 0ull, A1 = 0ull, A2 = 0ull, A3 = 0ull;
#pragma unroll
        for (int kc = 0; kc < 4; kc++) {
            // deposit regs into sh
            *reinterpret_cast<float4*>(&sh[lb0][lk0]) = r0;
            *reinterpret_cast<float4*>(&sh[lb1][lk0]) = r1;
            *reinterpret_cast<float4*>(&sh[lb2][lk0]) = r2;
            *reinterpret_cast<float4*>(&sh[lb3][lk0]) = r3;
            __syncthreads();
            const int kb = kc << 6;
            if (kc < 3) {
                const int kn = kb + 64;
                r0 = __ldcg(reinterpret_cast<const float4*>(&hin[lb0 * 256 + kn + lk0]));
                r1 = __ldcg(reinterpret_cast<const float4*>(&hin[lb1 * 256 + kn + lk0]));
                r2 = __ldcg(reinterpret_cast<const float4*>(&hin[lb2 * 256 + kn + lk0]));
                r3 = __ldcg(reinterpret_cast<const float4*>(&hin[lb3 * 256 + kn + lk0]));
            } else if (step < 511) {
                const int sn = dir ? (510 - step) : (step + 1);
                xv = *reinterpret_cast<const float4*>(
                    &g_Xperm[(((size_t)dir * Sn + sn) * 64 + blk) * 1024 + tid * 4]);
            }
#pragma unroll
            for (int kk = 0; kk < 16; kk++) {
                ulonglong2 hv = *reinterpret_cast<const ulonglong2*>(&sh[bh][kk * 4]);
                ulonglong2 w0 = *reinterpret_cast<const ulonglong2*>(&sW[jq4 + 0][kb + kk * 4]);
                ulonglong2 w1 = *reinterpret_cast<const ulonglong2*>(&sW[jq4 + 1][kb + kk * 4]);
                ulonglong2 w2 = *reinterpret_cast<const ulonglong2*>(&sW[jq4 + 2][kb + kk * 4]);
                ulonglong2 w3 = *reinterpret_cast<const ulonglong2*>(&sW[jq4 + 3][kb + kk * 4]);
                ffma2(A0, hv.x, w0.x); ffma2(A0, hv.y, w0.y);
                ffma2(A1, hv.x, w1.x); ffma2(A1, hv.y, w1.y);
                ffma2(A2, hv.x, w2.x); ffma2(A2, hv.y, w2.y);
                ffma2(A3, hv.x, w3.x); ffma2(A3, hv.y, w3.y);
            }
            __syncthreads();
        }
        // epilogue: accumulate into gates (distinct (b,j) per thread)
        sG[bh][jq4 + 0] += hsum2(A0);
        sG[bh][jq4 + 1] += hsum2(A1);
        sG[bh][jq4 + 2] += hsum2(A2);
        sG[bh][jq4 + 3] += hsum2(A3);
        __syncthreads();

        // pointwise LSTM cell update
        {
            float gi = sG[ub][0 + ur];
            float gf = sG[ub][4 + ur];
            float gg = sG[ub][8 + ur];
            float go = sG[ub][12 + ur];
            float c = sC[ub][ur];
            c = fsig(gf) * c + fsig(gi) * ftanh(gg);
            float h = fsig(go) * ftanh(c);
            sC[ub][ur] = c;
            const int hcol = (blk << 2) + ur;
            hout[ub * 256 + hcol] = h;
            g_Hbuf[(((size_t)dir * Sn + s) * Bn + ub) * Hn + hcol] = h;
        }
        // last step needs no cross-block publication (kernel boundary orders it)
        if (step < 511) dir_barrier(dir, blk, 2u + (unsigned)step);
    }

    // Reset barrier counters for the next launch: last block out does it.
    __syncthreads();
    if (tid == 0) {
        unsigned e = atomicAdd(&g_exit[dir], 1u);
        if (e == 63u) {
#pragma unroll
            for (int i = 0; i < 8; i++) g_cnt[dir][i][0] = 0u;
            g_exit[dir] = 0u;
        }
    }
}

// ---------------------------------------------------------------------------
// Kernel 3: emissions em[b][s][l] = [hf,hb] @ Wo + bo. One warp per (s,b).
// ---------------------------------------------------------------------------
__global__ void emissions_kernel(const float* __restrict__ Wo,
                                 const float* __restrict__ bo) {
    const int warp = (blockIdx.x * blockDim.x + threadIdx.x) >> 5;
    const int lane = threadIdx.x & 31;
    if (warp >= Bn * Sn) return;
    const int s = warp >> 6;
    const int b = warp & 63;
    const float* __restrict__ hf = &g_Hbuf[(((size_t)0 * Sn + s) * Bn + b) * Hn];
    const float* __restrict__ hb = &g_Hbuf[(((size_t)1 * Sn + s) * Bn + b) * Hn];

    float acc[9];
#pragma unroll
    for (int j = 0; j < 9; j++) acc[j] = 0.0f;

    for (int k = lane; k < 256; k += 32) {
        float vf = hf[k];
        float vb = hb[k];
        const float* w1 = &Wo[(size_t)k * Ln];
        const float* w2 = &Wo[(size_t)(256 + k) * Ln];
#pragma unroll
        for (int j = 0; j < 9; j++) acc[j] += vf * w1[j] + vb * w2[j];
    }
#pragma unroll
    for (int j = 0; j < 9; j++) {
        float v = acc[j];
#pragma unroll
        for (int o = 16; o; o >>= 1) v += __shfl_down_sync(0xffffffffu, v, o);
        if (lane == 0) g_em[((size_t)b * Sn + s) * Ln + j] = v + bo[j];
    }
}

// ---------------------------------------------------------------------------
// Kernel 4: CRF forward (register alpha + shfl broadcast) and gold score
// (t-parallel). One warp per batch.
// ---------------------------------------------------------------------------
__global__ void crf_kernel(const int* __restrict__ x,
                           const int* __restrict__ y,
                           const float* __restrict__ T,
                           const float* __restrict__ start,
                           const float* __restrict__ end) {
    const int b = blockIdx.x;
    const int lane = threadIdx.x;
    const float* __restrict__ em = &g_em[(size_t)b * Sn * Ln];
    const int* __restrict__ xb = &x[b * Sn];
    const int* __restrict__ yb = &y[b * Sn];
    const bool act = lane < 9;

    float Tcol[9];
    if (act) {
#pragma unroll
        for (int i = 0; i < 9; i++) Tcol[i] = T[i * 9 + lane];
    }
    float alpha = act ? (start[lane] + em[lane]) : -1e30f;

    for (int t = 1; t < Sn; t++) {
        int xt = __ldg(&xb[t]);
        float emt = act ? __ldg(&em[t * Ln + lane]) : 0.0f;
        float ai[9];
#pragma unroll
        for (int i = 0; i < 9; i++) ai[i] = __shfl_sync(0xffffffffu, alpha, i);
        if (xt != 0) {
            float v[9];
#pragma unroll
            for (int i = 0; i < 9; i++) v[i] = ai[i] + Tcol[i];
            float m01 = fmaxf(v[0], v[1]), m23 = fmaxf(v[2], v[3]);
            float m45 = fmaxf(v[4], v[5]), m67 = fmaxf(v[6], v[7]);
            float mx = fmaxf(fmaxf(fmaxf(m01, m23), fmaxf(m45, m67)), v[8]);
            float ssum = 0.0f;
#pragma unroll
            for (int i = 0; i < 9; i++) ssum += __expf(v[i] - mx);
            float na = mx + __logf(ssum) + emt;
            if (act) alpha = na;
        }
    }

    // logZ = logsumexp over 9 labels
    float vz = act ? (alpha + end[lane]) : -1e30f;
    float mx = vz;
#pragma unroll
    for (int o = 16; o; o >>= 1) mx = fmaxf(mx, __shfl_xor_sync(0xffffffffu, mx, o));
    float e = act ? __expf(vz - mx) : 0.0f;
#pragma unroll
    for (int o = 16; o; o >>= 1) e += __shfl_xor_sync(0xffffffffu, e, o);
    float logZ = mx + __logf(e);

    // gold score: t-parallel (prev label is y[t-1], no carried dependency)
    float gs = 0.0f;
    int cnt = 0;
    for (int t = lane; t < Sn; t += 32) {
        int m = (__ldg(&xb[t]) != 0) ? 1 : 0;
        cnt += m;
        if (t >= 1 && m) {
            int yt = __ldg(&yb[t]);
            int yp = __ldg(&yb[t - 1]);
            gs += T[yp * 9 + yt] + em[t * Ln + yt];
        }
    }
#pragma unroll
    for (int o = 16; o; o >>= 1) {
        gs  += __shfl_xor_sync(0xffffffffu, gs, o);
        cnt += __shfl_xor_sync(0xffffffffu, cnt, o);
    }

    if (lane == 0) {
        int y0 = yb[0];
        float score = start[y0] + em[y0] + gs;
        int last = cnt - 1;
        if (last < 0) last = 0;
        score += end[yb[last]];
        g_res[b] = logZ - score;
    }
}

// ---------------------------------------------------------------------------
// Kernel 5: mean over batch -> scalar output
// ---------------------------------------------------------------------------
__global__ void reduce_kernel(float* __restrict__ out) {
    __shared__ float s[64];
    s[threadIdx.x] = g_res[threadIdx.x];
    __syncthreads();
    if (threadIdx.x == 0) {
        float t = 0.0f;
        for (int i = 0; i < 64; i++) t += s[i];
        out[0] = t * (1.0f / 64.0f);
    }
}

// ---------------------------------------------------------------------------
extern "C" void kernel_launch(void* const* d_in, const int* in_sizes, int n_in,
                              void* d_out, int out_size) {
    const int*   x      = (const int*)  d_in[0];
    const int*   y      = (const int*)  d_in[1];
    const float* E      = (const float*)d_in[2];
    const float* Wih_f  = (const float*)d_in[3];
    const float* Whh_f  = (const float*)d_in[4];
    const float* b_f    = (const float*)d_in[5];
    const float* Wih_b  = (const float*)d_in[6];
    const float* Whh_b  = (const float*)d_in[7];
    const float* b_b    = (const float*)d_in[8];
    const float* Wo     = (const float*)d_in[9];
    const float* bo     = (const float*)d_in[10];
    const float* T      = (const float*)d_in[11];
    const float* start  = (const float*)d_in[12];
    const float* end    = (const float*)d_in[13];
    float* out = (float*)d_out;

    dim3 gemm_grid(8, 512, 2);
    embed_inproj_kernel<<<gemm_grid, 256>>>(x, E, Wih_f, b_f, Wih_b, b_b);
    lstm_recur_kernel<<<128, 256>>>(Whh_f, Whh_b);
    emissions_kernel<<<4096, 256>>>(Wo, bo);
    crf_kernel<<<64, 32>>>(x, y, T, start, end);
    reduce_kernel<<<1, 64>>>(out);
}